// round 13
// baseline (speedup 1.0000x reference)
#include <cuda_runtime.h>
#include <cuda_fp16.h>
#include <mma.h>
#include <math.h>
#include <stdint.h>

using namespace nvcuda;

#define D_MODEL 1024
#define NHEAD 16
#define HEAD_DIM 64
#define HIDDEN 4096
#define BATCH 2
#define SEQ 2048
#define ROWS (BATCH * SEQ)   // 4096

// ---------------- scratch (allocation-free: __device__ globals) ----------------
__device__ float  g_x1 [(size_t)ROWS * D_MODEL];
__device__ __half g_qkvh[(size_t)ROWS * 3 * D_MODEL];
__device__ __half g_hh [(size_t)ROWS * 2 * HIDDEN];
__device__ __half g_xn  [(size_t)ROWS * D_MODEL];
__device__ __half g_att [(size_t)ROWS * D_MODEL];
__device__ __half g_ffn [(size_t)ROWS * HIDDEN];
// transposed fp16 weights [N,K], concatenated:
//   [0)        qkvT  3072x1024
//   [3145728)  oT    1024x1024
//   [4194304)  w1T   8192x1024
//   [12582912) w2T   1024x4096
__device__ __half g_wt[16777216];

// ---------------- helpers ----------------
__device__ __forceinline__ uint32_t smem_u32(const void* p) {
    uint32_t a;
    asm("{ .reg .u64 t; cvta.to.shared.u64 t, %1; cvt.u32.u64 %0, t; }"
        : "=r"(a) : "l"(p));
    return a;
}
__device__ __forceinline__ void cp16(void* dst_smem, const void* src) {
    uint32_t d = smem_u32(dst_smem);
    asm volatile("cp.async.cg.shared.global [%0], [%1], 16;" :: "r"(d), "l"(src));
}
__device__ __forceinline__ void cp_commit() {
    asm volatile("cp.async.commit_group;" ::: "memory");
}
template<int N> __device__ __forceinline__ void cp_wait() {
    asm volatile("cp.async.wait_group %0;" :: "n"(N) : "memory");
}

// ---------------- weight transpose + fp16: W[K,N] -> Wt [N,K] ----------------
__global__ __launch_bounds__(256) void wsplit_kernel(
    const float* __restrict__ W, int K, int N, __half* __restrict__ T)
{
    __shared__ float t[32][33];
    int tx = threadIdx.x & 31, ty = threadIdx.x >> 5;  // 32x8
    int n0 = blockIdx.x * 32, k0 = blockIdx.y * 32;
    #pragma unroll
    for (int j = 0; j < 4; j++)
        t[ty + j * 8][tx] = W[(size_t)(k0 + ty + j * 8) * N + n0 + tx];
    __syncthreads();
    #pragma unroll
    for (int j = 0; j < 4; j++) {
        int n = n0 + ty + j * 8, k = k0 + tx;
        T[(size_t)n * K + k] = __float2half_rn(t[tx][ty + j * 8]);
    }
}

// ---------------- RMSNorm -> fp16 ----------------
__global__ __launch_bounds__(256) void rmsnorm_kernel(
    const float* __restrict__ x, const float* __restrict__ scale,
    __half* __restrict__ y)
{
    int row = blockIdx.x;
    const float* xr = x + (size_t)row * D_MODEL;
    int t = threadIdx.x;
    float v0 = xr[t], v1 = xr[t + 256], v2 = xr[t + 512], v3 = xr[t + 768];
    float ss = v0*v0 + v1*v1 + v2*v2 + v3*v3;
    #pragma unroll
    for (int o = 16; o; o >>= 1) ss += __shfl_xor_sync(0xffffffffu, ss, o);
    __shared__ float red[8];
    if ((t & 31) == 0) red[t >> 5] = ss;
    __syncthreads();
    float tot = 0.f;
    #pragma unroll
    for (int w = 0; w < 8; w++) tot += red[w];
    float r = rsqrtf(tot * (1.0f / D_MODEL) + 1e-8f);
    size_t base = (size_t)row * D_MODEL;
    y[base + t]       = __float2half_rn(scale[t]       * v0 * r);
    y[base + t + 256] = __float2half_rn(scale[t + 256] * v1 * r);
    y[base + t + 512] = __float2half_rn(scale[t + 512] * v2 * r);
    y[base + t + 768] = __float2half_rn(scale[t + 768] * v3 * r);
}

// ---------------- wmma fp16 GEMM (3-stage): C = A[M,K] @ Bt[N,K]^T + bias (+res) ----
// CTA 128x128, 8 warps (4x2), warp tile 32x64 = 2x4 wmma 16x16x16 frags.
// BK=32, cp.async 3-stage, single barrier per stage.
// Output: fp32 (C, +res) or fp16 (Ch) — exactly one of C/Ch non-null.
#define BKP 40
#define TILE_E (128 * BKP)                 // half elems per tile (5120)
#define STG_E  (2 * TILE_E)                // elems per stage (A,B) = 10240 (20480 B)
#define GSMEM  61440                       // 3 stages; epilogue staging 36864 < this

#define GEMM_ISSUE(sidx)                                                   \
    {                                                                      \
        __half* st = sm + ((sidx) % 3) * STG_E;                            \
        size_t go = (size_t)ld_row * K + ((sidx) << 5) + ld_seg * 8;       \
        uint32_t so = ld_row * BKP + ld_seg * 8;                           \
        cp16(st + so,              gb0 + go);                              \
        cp16(st + so + 8,          gb0 + go + 8);                          \
        cp16(st + TILE_E + so,     gb1 + go);                              \
        cp16(st + TILE_E + so + 8, gb1 + go + 8);                          \
        cp_commit();                                                      \
    }

__global__ __launch_bounds__(256) void wmma_gemm(
    const __half* __restrict__ A, const __half* __restrict__ B,
    const float* __restrict__ bias, const float* __restrict__ res,
    float* __restrict__ C, __half* __restrict__ Ch, int M, int N, int K)
{
    extern __shared__ __align__(128) __half sm[];
    int tid = threadIdx.x, wid = tid >> 5, lane = tid & 31;
    int bm = blockIdx.y, bn = blockIdx.x;
    int wm = wid >> 1, wn = wid & 1;

    wmma::fragment<wmma::accumulator, 16, 16, 16, float> acc[2][4];
    #pragma unroll
    for (int i = 0; i < 2; i++)
        #pragma unroll
        for (int j = 0; j < 4; j++) wmma::fill_fragment(acc[i][j], 0.f);

    const __half* gb0 = A + (size_t)bm * 128 * K;
    const __half* gb1 = B + (size_t)bn * 128 * K;

    const int S = K >> 5;
    int ld_row = tid >> 1;              // 0..127
    int ld_seg = (tid & 1) << 1;        // 0 or 2

    GEMM_ISSUE(0);
    GEMM_ISSUE(1);

    for (int s = 0; s < S; s++) {
        if (s + 1 < S) cp_wait<1>(); else cp_wait<0>();
        __syncthreads();
        if (s + 2 < S) GEMM_ISSUE(s + 2);

        const __half* st = sm + (s % 3) * STG_E;
        const __half* As = st;
        const __half* Bs = st + TILE_E;

        #pragma unroll
        for (int kk = 0; kk < 32; kk += 16) {
            wmma::fragment<wmma::matrix_a, 16, 16, 16, __half, wmma::row_major> a[2];
            wmma::fragment<wmma::matrix_b, 16, 16, 16, __half, wmma::col_major> b[4];
            #pragma unroll
            for (int i = 0; i < 2; i++)
                wmma::load_matrix_sync(a[i], As + (wm * 32 + i * 16) * BKP + kk, BKP);
            #pragma unroll
            for (int j = 0; j < 4; j++)
                wmma::load_matrix_sync(b[j], Bs + (wn * 64 + j * 16) * BKP + kk, BKP);
            #pragma unroll
            for (int i = 0; i < 2; i++)
                #pragma unroll
                for (int j = 0; j < 4; j++)
                    wmma::mma_sync(acc[i][j], a[i], b[j], acc[i][j]);
        }
    }
    __syncthreads();   // stage buffers are reused as epilogue staging below

    // epilogue: per-warp staging (32 rows x 36 floats), two 32-col waves
    float* stg  = (float*)sm;
    float* wstg = stg + wid * 32 * 36;
    int row = bm * 128 + wm * 32 + lane;
    #pragma unroll
    for (int hn = 0; hn < 2; hn++) {
        #pragma unroll
        for (int i = 0; i < 2; i++)
            #pragma unroll
            for (int j = 0; j < 2; j++)
                wmma::store_matrix_sync(wstg + i * 16 * 36 + j * 16,
                                        acc[i][hn * 2 + j], 36, wmma::mem_row_major);
        __syncwarp();
        int col0 = bn * 128 + wn * 64 + hn * 32;
        const float* srow = wstg + lane * 36;
        const float* br = bias + col0;
        if (Ch) {
            __half* Cr = Ch + (size_t)row * N + col0;
            #pragma unroll
            for (int c = 0; c < 32; c += 2) {
                __half2 hv = __floats2half2_rn(srow[c] + br[c], srow[c+1] + br[c+1]);
                *(__half2*)(Cr + c) = hv;
            }
        } else {
            float* Cr = C + (size_t)row * N + col0;
            const float* rr = res ? res + (size_t)row * N + col0 : nullptr;
            #pragma unroll
            for (int c = 0; c < 32; c += 4) {
                float4 o = *(const float4*)(srow + c);
                float4 bv = *(const float4*)(br + c);
                o.x += bv.x; o.y += bv.y; o.z += bv.z; o.w += bv.w;
                if (rr) {
                    float4 rv = *(const float4*)(rr + c);
                    o.x += rv.x; o.y += rv.y; o.z += rv.z; o.w += rv.w;
                }
                *(float4*)(Cr + c) = o;
            }
        }
        __syncwarp();
    }
}

// ---------------- Flash attention via wmma (causal + analytic ALiBi), fp16 qkv ----
#define AP 72    // half pad for Q,K,V,P rows
#define SP 68    // float pad for S,O rows
#define FA_SMEM (4*64*AP*2 + 2*64*SP*4 + 2*64*4)   // 72192

__global__ __launch_bounds__(256) void flash_wmma_kernel(
    const __half* __restrict__ qkv, __half* __restrict__ outp)
{
    extern __shared__ __align__(128) char smraw[];
    __half* Qh = (__half*)smraw;           // 64*AP
    __half* Kh = Qh + 64 * AP;
    __half* Vh = Kh + 64 * AP;
    __half* Ph = Vh + 64 * AP;
    float*  Sf = (float*)(Ph + 64 * AP);   // 64*SP
    float*  Of = Sf + 64 * SP;             // 64*SP
    float*  mrow = Of + 64 * SP;           // 64
    float*  lrow = mrow + 64;              // 64

    int qt = blockIdx.x;
    int bh = blockIdx.y;
    int b  = bh >> 4, h = bh & 15;
    float slope = exp2f(-0.5f * (float)(h + 1));

    int tid = threadIdx.x, wid = tid >> 5;
    int rw = wid >> 1, cb0 = (wid & 1) * 2;
    int r  = tid >> 2, cg = tid & 3;       // row r, 16-col group cg

    // load Q tile (fp16, direct copy)
    {
        int cl = cg << 4;
        const __half* src = qkv + (size_t)(b * SEQ + qt * 64 + r) * 3072 + h * 64 + cl;
        __half* dst = Qh + r * AP + cl;
        *(uint4*)dst       = *(const uint4*)src;
        *(uint4*)(dst + 8) = *(const uint4*)(src + 8);
    }
    for (int i = tid; i < 64 * SP; i += 256) Of[i] = 0.f;
    if (tid < 64) { mrow[tid] = -1e30f; lrow[tid] = 0.f; }
    __syncthreads();

    for (int kt = 0; kt <= qt; kt++) {
        // load K,V tiles (fp16, direct copy)
        {
            int cl = cg << 4;
            const __half* sk = qkv + (size_t)(b * SEQ + kt * 64 + r) * 3072 + 1024 + h * 64 + cl;
            const __half* sv = sk + 1024;
            __half* dk = Kh + r * AP + cl;
            __half* dv = Vh + r * AP + cl;
            *(uint4*)dk       = *(const uint4*)sk;
            *(uint4*)(dk + 8) = *(const uint4*)(sk + 8);
            *(uint4*)dv       = *(const uint4*)sv;
            *(uint4*)(dv + 8) = *(const uint4*)(sv + 8);
        }
        __syncthreads();

        // S = Q @ K^T (fp32 acc)
        {
            wmma::fragment<wmma::accumulator, 16, 16, 16, float> c[2];
            #pragma unroll
            for (int j = 0; j < 2; j++) wmma::fill_fragment(c[j], 0.f);
            #pragma unroll
            for (int ks = 0; ks < 4; ks++) {
                wmma::fragment<wmma::matrix_a, 16, 16, 16, __half, wmma::row_major> a;
                wmma::load_matrix_sync(a, Qh + rw * 16 * AP + ks * 16, AP);
                #pragma unroll
                for (int j = 0; j < 2; j++) {
                    wmma::fragment<wmma::matrix_b, 16, 16, 16, __half, wmma::col_major> bk;
                    wmma::load_matrix_sync(bk, Kh + (cb0 + j) * 16 * AP + ks * 16, AP);
                    wmma::mma_sync(c[j], a, bk, c[j]);
                }
            }
            #pragma unroll
            for (int j = 0; j < 2; j++)
                wmma::store_matrix_sync(Sf + rw * 16 * SP + (cb0 + j) * 16, c[j],
                                        SP, wmma::mem_row_major);
        }
        __syncthreads();

        // softmax pass (scalar, fp32) + scale O rows + P -> fp16
        {
            int iq = qt * 64 + r;
            int jb = kt * 64 + (cg << 4);
            float* srow = Sf + r * SP + (cg << 4);
            float vals[16];
            float mloc = -1e30f;
            #pragma unroll
            for (int c = 0; c < 16; c++) {
                int jj = jb + c;
                float val = srow[c] * 0.125f - slope * (float)(iq - jj);
                if (jj > iq) val = -1e30f;
                vals[c] = val;
                mloc = fmaxf(mloc, val);
            }
            mloc = fmaxf(mloc, __shfl_xor_sync(0xffffffffu, mloc, 1));
            mloc = fmaxf(mloc, __shfl_xor_sync(0xffffffffu, mloc, 2));
            float mold = mrow[r];
            float mnew = fmaxf(mold, mloc);
            float corr = __expf(mold - mnew);
            float ps = 0.f;
            __half* prow = Ph + r * AP + (cg << 4);
            #pragma unroll
            for (int c = 0; c < 16; c++) {
                float p = __expf(vals[c] - mnew);
                prow[c] = __float2half_rn(p);
                ps += p;
            }
            ps += __shfl_xor_sync(0xffffffffu, ps, 1);
            ps += __shfl_xor_sync(0xffffffffu, ps, 2);
            float* orow = Of + r * SP + (cg << 4);
            #pragma unroll
            for (int c = 0; c < 16; c++) orow[c] *= corr;
            if (cg == 0) { mrow[r] = mnew; lrow[r] = lrow[r] * corr + ps; }
        }
        __syncthreads();

        // O += P @ V (fp32 acc through smem)
        {
            wmma::fragment<wmma::accumulator, 16, 16, 16, float> oa[2];
            #pragma unroll
            for (int j = 0; j < 2; j++)
                wmma::load_matrix_sync(oa[j], Of + rw * 16 * SP + (cb0 + j) * 16,
                                       SP, wmma::mem_row_major);
            #pragma unroll
            for (int ks = 0; ks < 4; ks++) {
                wmma::fragment<wmma::matrix_a, 16, 16, 16, __half, wmma::row_major> pa;
                wmma::load_matrix_sync(pa, Ph + rw * 16 * AP + ks * 16, AP);
                #pragma unroll
                for (int j = 0; j < 2; j++) {
                    wmma::fragment<wmma::matrix_b, 16, 16, 16, __half, wmma::row_major> vb;
                    wmma::load_matrix_sync(vb, Vh + ks * 16 * AP + (cb0 + j) * 16, AP);
                    wmma::mma_sync(oa[j], pa, vb, oa[j]);
                }
            }
            #pragma unroll
            for (int j = 0; j < 2; j++)
                wmma::store_matrix_sync(Of + rw * 16 * SP + (cb0 + j) * 16, oa[j],
                                        SP, wmma::mem_row_major);
        }
        __syncthreads();
    }

    // epilogue: normalize, write fp16
    {
        float inv = 1.0f / lrow[r];
        const float* orow = Of + r * SP + (cg << 4);
        size_t off = (size_t)(b * SEQ + qt * 64 + r) * D_MODEL + h * 64 + (cg << 4);
        #pragma unroll
        for (int c = 0; c < 16; c++)
            outp[off + c] = __float2half_rn(orow[c] * inv);
    }
}

// ---------------- SwiGLU (fp16 in) -> fp16 ----------------
__global__ __launch_bounds__(256) void swiglu_kernel(
    const __half* __restrict__ h, __half* __restrict__ g)
{
    int idx = blockIdx.x * 256 + threadIdx.x;
    int r = idx >> 12;
    int j = idx & 4095;
    const __half* hr = h + (size_t)r * (2 * HIDDEN);
    float xp = __half2float(hr[j]);
    float gt = __half2float(hr[j + HIDDEN]);
    float sg = 1.0f / (1.0f + __expf(-gt));
    g[idx] = __float2half_rn(gt * sg * xp);
}

// ---------------- launch ----------------
extern "C" void kernel_launch(void* const* d_in, const int* in_sizes, int n_in,
                              void* d_out, int out_size)
{
    const float* x      = (const float*)d_in[0];
    const float* w_qkv  = (const float*)d_in[3];
    const float* b_qkv  = (const float*)d_in[4];
    const float* w_o    = (const float*)d_in[5];
    const float* b_o    = (const float*)d_in[6];
    const float* scale1 = (const float*)d_in[7];
    const float* scale2 = (const float*)d_in[8];
    const float* w1     = (const float*)d_in[9];
    const float* b1     = (const float*)d_in[10];
    const float* w2     = (const float*)d_in[11];
    const float* b2     = (const float*)d_in[12];
    float* out = (float*)d_out;

    float *x1;
    __half *qkvh, *hh, *xn, *att, *ffn, *wt;
    cudaGetSymbolAddress((void**)&x1,   g_x1);
    cudaGetSymbolAddress((void**)&qkvh, g_qkvh);
    cudaGetSymbolAddress((void**)&hh,   g_hh);
    cudaGetSymbolAddress((void**)&xn,   g_xn);
    cudaGetSymbolAddress((void**)&att,  g_att);
    cudaGetSymbolAddress((void**)&ffn,  g_ffn);
    cudaGetSymbolAddress((void**)&wt,   g_wt);

    cudaFuncSetAttribute(wmma_gemm, cudaFuncAttributeMaxDynamicSharedMemorySize, GSMEM);
    cudaFuncSetAttribute(flash_wmma_kernel,
                         cudaFuncAttributeMaxDynamicSharedMemorySize, FA_SMEM);

    const size_t OFF_QKV = 0, OFF_O = 3145728, OFF_W1 = 4194304, OFF_W2 = 12582912;

    // 0) transpose weights -> fp16
    wsplit_kernel<<<dim3(3072/32, 1024/32), 256>>>(w_qkv, 1024, 3072, wt+OFF_QKV);
    wsplit_kernel<<<dim3(1024/32, 1024/32), 256>>>(w_o,   1024, 1024, wt+OFF_O);
    wsplit_kernel<<<dim3(8192/32, 1024/32), 256>>>(w1,    1024, 8192, wt+OFF_W1);
    wsplit_kernel<<<dim3(1024/32, 4096/32), 256>>>(w2,    4096, 1024, wt+OFF_W2);

    // 1) xn = rmsnorm(x, scale1) -> fp16
    rmsnorm_kernel<<<ROWS, 256>>>(x, scale1, xn);
    // 2) qkv = xn @ w_qkv + b_qkv -> fp16
    wmma_gemm<<<dim3(3072/128, ROWS/128), 256, GSMEM>>>(
        xn, wt+OFF_QKV, b_qkv, nullptr, nullptr, qkvh, ROWS, 3072, 1024);
    // 3) attention (wmma, fp16 in/out)
    flash_wmma_kernel<<<dim3(SEQ/64, BATCH*NHEAD), 256, FA_SMEM>>>(qkvh, att);
    // 4) x1 = x + att @ w_o + b_o  (fp32)
    wmma_gemm<<<dim3(1024/128, ROWS/128), 256, GSMEM>>>(
        att, wt+OFF_O, b_o, x, x1, nullptr, ROWS, 1024, 1024);
    // 5) xn = rmsnorm(x1, scale2) -> fp16
    rmsnorm_kernel<<<ROWS, 256>>>(x1, scale2, xn);
    // 6) h = xn @ w1 + b1 -> fp16
    wmma_gemm<<<dim3(8192/128, ROWS/128), 256, GSMEM>>>(
        xn, wt+OFF_W1, b1, nullptr, nullptr, hh, ROWS, 8192, 1024);
    // 7) ffn = silu(gate) * x_proj -> fp16
    swiglu_kernel<<<ROWS * HIDDEN / 256, 256>>>(hh, ffn);
    // 8) out = x1 + ffn @ w2 + b2  (fp32)
    wmma_gemm<<<dim3(1024/128, ROWS/128), 256, GSMEM>>>(
        ffn, wt+OFF_W2, b2, x1, out, nullptr, ROWS, 1024, 4096);
}